// round 4
// baseline (speedup 1.0000x reference)
#include <cuda_runtime.h>
#include <cuda_fp16.h>
#include <math.h>

#define NN   1024
#define HH   128
#define DD   256
#define NLVL 3
#define LN_EPS 1e-5f

// -------- device scratch (static: allocation-free kernel_launch) --------
__device__ float g_x[NN*HH];        // node features, updated per level
__device__ float g_pre[NN*HH];      // x@Wi + msg_b  (b folded in)
__device__ float g_prj[NN*HH];      // x@Wj
__device__ float g_msum[NN*HH];
__device__ float g_lmean[NLVL*HH];  // per-level mean of x
__device__ __half g_ew[(long long)NN*NN*HH];  // 256 MB, level-invariant edge weights (fp16)

// silu(x) = 0.5*x*(1 + tanh(0.5*x))  — 1 MUFU instead of 2
__device__ __forceinline__ float silu_f(float x) {
    float t;
    asm("tanh.approx.f32 %0, %1;" : "=f"(t) : "f"(x * 0.5f));
    float hx = 0.5f * x;
    return fmaf(hx, t, hx);
}

// ---------------------------------------------------------------
// init: zero level means, gather x0 = emb[atomic_numbers]
__global__ void k_init(const int* __restrict__ an, const float* __restrict__ emb) {
    int t = blockIdx.x * blockDim.x + threadIdx.x;
    if (t < NLVL*HH) g_lmean[t] = 0.f;
    int n = t >> 7;
    int h = t & 127;
    g_x[t] = emb[an[n]*HH + h];
}

// ---------------------------------------------------------------
// ew[i,j,:] = LN(silu(scales(i,j) @ de_W + de_b)) * de_g + de_be   (fp16 out)
// Symmetric in (i,j): compute j>=i only, write both mirrors.
// one warp per (i,j); 4 h per lane. grid (128, 1024), block 256.
__global__ void __launch_bounds__(256) k_ew(
    const float* __restrict__ pos,
    const float* __restrict__ deW, const float* __restrict__ deb,
    const float* __restrict__ deg, const float* __restrict__ debe)
{
    int warp = threadIdx.x >> 5;
    int lane = threadIdx.x & 31;
    int i = blockIdx.y;
    int j = (blockIdx.x << 3) + warp;
    if (j < i) return;   // symmetry: handle upper triangle incl. diagonal

    float dx = pos[3*i]   - pos[3*j];
    float dy = pos[3*i+1] - pos[3*j+1];
    float dz = pos[3*i+2] - pos[3*j+2];
    float sq = dx*dx + dy*dy + dz*dz;
    float d  = (sq > 0.f) ? sqrtf(sq) : 0.f;
    float s3 = __expf(-0.25f * d);   // exp(-d/4)
    float s2 = s3 * s3;              // exp(-d/2)
    float s1 = s2 * s2;              // exp(-d)

    int h0 = lane << 2;
    float4 w0 = *(const float4*)(deW + h0);
    float4 w1 = *(const float4*)(deW + HH + h0);
    float4 w2 = *(const float4*)(deW + 2*HH + h0);
    float4 bb = *(const float4*)(deb + h0);

    float v0 = fmaf(s1, w0.x, fmaf(s2, w1.x, fmaf(s3, w2.x, bb.x)));
    float v1 = fmaf(s1, w0.y, fmaf(s2, w1.y, fmaf(s3, w2.y, bb.y)));
    float v2 = fmaf(s1, w0.z, fmaf(s2, w1.z, fmaf(s3, w2.z, bb.z)));
    float v3 = fmaf(s1, w0.w, fmaf(s2, w1.w, fmaf(s3, w2.w, bb.w)));

    v0 = silu_f(v0); v1 = silu_f(v1); v2 = silu_f(v2); v3 = silu_f(v3);

    float p = v0 + v1 + v2 + v3;
    float q = fmaf(v0,v0, fmaf(v1,v1, fmaf(v2,v2, v3*v3)));
    #pragma unroll
    for (int off = 16; off; off >>= 1) {
        p += __shfl_xor_sync(0xffffffffu, p, off);
        q += __shfl_xor_sync(0xffffffffu, q, off);
    }
    float mu   = p * (1.f/HH);
    float var  = fmaf(-mu, mu, q * (1.f/HH));
    float rstd = rsqrtf(var + LN_EPS);

    float4 gg = *(const float4*)(deg + h0);
    float4 be = *(const float4*)(debe + h0);
    float o0 = fmaf((v0 - mu) * rstd, gg.x, be.x);
    float o1 = fmaf((v1 - mu) * rstd, gg.y, be.y);
    float o2 = fmaf((v2 - mu) * rstd, gg.z, be.z);
    float o3 = fmaf((v3 - mu) * rstd, gg.w, be.w);

    __half2 ha = __floats2half2_rn(o0, o1);
    __half2 hb = __floats2half2_rn(o2, o3);
    __half2* dst0 = (__half2*)(g_ew + ((long long)i*NN + j)*HH + h0);
    dst0[0] = ha; dst0[1] = hb;
    if (j != i) {
        __half2* dst1 = (__half2*)(g_ew + ((long long)j*NN + i)*HH + h0);
        dst1[0] = ha; dst1[1] = hb;
    }
}

// ---------------------------------------------------------------
// pre = x@Wi + msg_b, prj = x@Wj.  8 nodes per block, 128 threads (h).
__global__ void __launch_bounds__(128) k_preprj(
    const float* __restrict__ msgW, const float* __restrict__ msgb, int lvl)
{
    __shared__ float xs[8][HH];
    int h  = threadIdx.x;
    int n0 = blockIdx.x << 3;
    #pragma unroll
    for (int nn = 0; nn < 8; nn++) xs[nn][h] = g_x[(n0+nn)*HH + h];
    __syncthreads();

    const float* Wi = msgW + (size_t)lvl*2*HH*HH;
    const float* Wj = Wi + HH*HH;
    float ai[8], aj[8];
    #pragma unroll
    for (int nn = 0; nn < 8; nn++) { ai[nn] = 0.f; aj[nn] = 0.f; }

    for (int k = 0; k < HH; k++) {
        float wi = Wi[k*HH + h];
        float wj = Wj[k*HH + h];
        #pragma unroll
        for (int nn = 0; nn < 8; nn++) {
            ai[nn] = fmaf(xs[nn][k], wi, ai[nn]);
            aj[nn] = fmaf(xs[nn][k], wj, aj[nn]);
        }
    }
    float bb = msgb[lvl*HH + h];
    #pragma unroll
    for (int nn = 0; nn < 8; nn++) {
        g_pre[(n0+nn)*HH + h] = ai[nn] + bb;
        g_prj[(n0+nn)*HH + h] = aj[nn];
    }
}

// ---------------------------------------------------------------
// msum[i,h] = sum_j LN(silu(pre_i + prj_j))_h * ew[i,j,h]
// one block per i, 8 warps striding j, 4 h per lane.
__global__ void __launch_bounds__(256) k_msum(
    const float* __restrict__ msgg, const float* __restrict__ msgbe, int lvl)
{
    __shared__ float red[8][HH];
    int i    = blockIdx.x;
    int warp = threadIdx.x >> 5;
    int lane = threadIdx.x & 31;
    int h0   = lane << 2;

    float4 pre4 = *(const float4*)(g_pre + i*HH + h0);
    float4 gg   = *(const float4*)(msgg  + lvl*HH + h0);
    float4 bb   = *(const float4*)(msgbe + lvl*HH + h0);

    float a0 = 0.f, a1 = 0.f, a2 = 0.f, a3 = 0.f;
    const __half2* ewrow = (const __half2*)(g_ew + (long long)i*NN*HH) + (h0 >> 1);

    for (int j = warp; j < NN; j += 8) {
        float4 pj = *(const float4*)(g_prj + j*HH + h0);
        float s0 = silu_f(pre4.x + pj.x);
        float s1 = silu_f(pre4.y + pj.y);
        float s2 = silu_f(pre4.z + pj.z);
        float s3 = silu_f(pre4.w + pj.w);

        float p = s0 + s1 + s2 + s3;
        float q = fmaf(s0,s0, fmaf(s1,s1, fmaf(s2,s2, s3*s3)));
        #pragma unroll
        for (int off = 16; off; off >>= 1) {
            p += __shfl_xor_sync(0xffffffffu, p, off);
            q += __shfl_xor_sync(0xffffffffu, q, off);
        }
        float mu   = p * (1.f/HH);
        float var  = fmaf(-mu, mu, q * (1.f/HH));
        float rstd = rsqrtf(var + LN_EPS);

        const __half2* e2 = ewrow + (long long)j*(HH/2);
        float2 e01 = __half22float2(e2[0]);
        float2 e23 = __half22float2(e2[1]);
        a0 = fmaf(fmaf((s0-mu)*rstd, gg.x, bb.x), e01.x, a0);
        a1 = fmaf(fmaf((s1-mu)*rstd, gg.y, bb.y), e01.y, a1);
        a2 = fmaf(fmaf((s2-mu)*rstd, gg.z, bb.z), e23.x, a2);
        a3 = fmaf(fmaf((s3-mu)*rstd, gg.w, bb.w), e23.y, a3);
    }

    red[warp][h0+0] = a0; red[warp][h0+1] = a1;
    red[warp][h0+2] = a2; red[warp][h0+3] = a3;
    __syncthreads();
    if (threadIdx.x < HH) {
        int h = threadIdx.x;
        float s = 0.f;
        #pragma unroll
        for (int w = 0; w < 8; w++) s += red[w][h];
        g_msum[i*HH + h] = s;
    }
}

// ---------------------------------------------------------------
// x += LN(silu([x, msum] @ upd_W + upd_b)); accumulate level mean.
__global__ void __launch_bounds__(128) k_upd(
    const float* __restrict__ updW, const float* __restrict__ updb,
    const float* __restrict__ updg, const float* __restrict__ updbe, int lvl)
{
    __shared__ float us[2*HH];
    __shared__ float rp[4], rq[4];
    __shared__ float s_mu, s_rstd;
    int i = blockIdx.x;
    int h = threadIdx.x;
    int warp = h >> 5, lane = h & 31;

    us[h]      = g_x[i*HH + h];
    us[HH + h] = g_msum[i*HH + h];
    __syncthreads();

    const float* W = updW + (size_t)lvl*2*HH*HH;
    float acc = updb[lvl*HH + h];
    #pragma unroll 4
    for (int k = 0; k < 2*HH; k++) acc = fmaf(us[k], W[k*HH + h], acc);

    float s = silu_f(acc);

    float p = s, q = s*s;
    #pragma unroll
    for (int off = 16; off; off >>= 1) {
        p += __shfl_xor_sync(0xffffffffu, p, off);
        q += __shfl_xor_sync(0xffffffffu, q, off);
    }
    if (lane == 0) { rp[warp] = p; rq[warp] = q; }
    __syncthreads();
    if (h == 0) {
        float P = rp[0]+rp[1]+rp[2]+rp[3];
        float Q = rq[0]+rq[1]+rq[2]+rq[3];
        float mu = P * (1.f/HH);
        s_mu = mu;
        s_rstd = rsqrtf(fmaf(-mu, mu, Q * (1.f/HH)) + LN_EPS);
    }
    __syncthreads();

    float m  = fmaf((s - s_mu) * s_rstd, updg[lvl*HH + h], updbe[lvl*HH + h]);
    float xn = us[h] + m;
    g_x[i*HH + h] = xn;
    atomicAdd(&g_lmean[lvl*HH + h], xn * (1.f/NN));
}

// ---------------------------------------------------------------
// out = LN(concat(level_means) @ fp_W + fp_b) * fp_g + fp_be
__global__ void __launch_bounds__(256) k_final(
    const float* __restrict__ fpW, const float* __restrict__ fpb,
    const float* __restrict__ fpg, const float* __restrict__ fpbe,
    float* __restrict__ out)
{
    __shared__ float cs[NLVL*HH];
    __shared__ float rp[8], rq[8];
    __shared__ float s_mu, s_rstd;
    int t = threadIdx.x;
    int warp = t >> 5, lane = t & 31;

    // NLVL*HH = 384 > blockDim (256): strided load.
    for (int k = t; k < NLVL*HH; k += 256) cs[k] = g_lmean[k];
    __syncthreads();

    float acc = fpb[t];
    #pragma unroll 4
    for (int k = 0; k < NLVL*HH; k++) acc = fmaf(cs[k], fpW[k*DD + t], acc);

    float p = acc, q = acc*acc;
    #pragma unroll
    for (int off = 16; off; off >>= 1) {
        p += __shfl_xor_sync(0xffffffffu, p, off);
        q += __shfl_xor_sync(0xffffffffu, q, off);
    }
    if (lane == 0) { rp[warp] = p; rq[warp] = q; }
    __syncthreads();
    if (t == 0) {
        float P = 0.f, Q = 0.f;
        #pragma unroll
        for (int w = 0; w < 8; w++) { P += rp[w]; Q += rq[w]; }
        float mu = P * (1.f/DD);
        s_mu = mu;
        s_rstd = rsqrtf(fmaf(-mu, mu, Q * (1.f/DD)) + LN_EPS);
    }
    __syncthreads();

    out[t] = fmaf((acc - s_mu) * s_rstd, fpg[t], fpbe[t]);
}

// ---------------------------------------------------------------
extern "C" void kernel_launch(void* const* d_in, const int* in_sizes, int n_in,
                              void* d_out, int out_size) {
    const int*   an    = (const int*)  d_in[0];
    const float* pos   = (const float*)d_in[1];
    const float* emb   = (const float*)d_in[2];
    const float* deW   = (const float*)d_in[3];
    const float* deb   = (const float*)d_in[4];
    const float* deg   = (const float*)d_in[5];
    const float* debe  = (const float*)d_in[6];
    const float* msgW  = (const float*)d_in[7];
    const float* msgb  = (const float*)d_in[8];
    const float* msgg  = (const float*)d_in[9];
    const float* msgbe = (const float*)d_in[10];
    const float* updW  = (const float*)d_in[11];
    const float* updb  = (const float*)d_in[12];
    const float* updg  = (const float*)d_in[13];
    const float* updbe = (const float*)d_in[14];
    const float* fpW   = (const float*)d_in[15];
    const float* fpb   = (const float*)d_in[16];
    const float* fpg   = (const float*)d_in[17];
    const float* fpbe  = (const float*)d_in[18];
    float* out = (float*)d_out;

    k_init<<<512, 256>>>(an, emb);
    k_ew<<<dim3(128, 1024), 256>>>(pos, deW, deb, deg, debe);
    for (int lvl = 0; lvl < NLVL; lvl++) {
        k_preprj<<<128, 128>>>(msgW, msgb, lvl);
        k_msum<<<1024, 256>>>(msgg, msgbe, lvl);
        k_upd<<<1024, 128>>>(updW, updb, updg, updbe, lvl);
    }
    k_final<<<1, 256>>>(fpW, fpb, fpg, fpbe, out);
}

// round 7
// speedup vs baseline: 1.7224x; 1.7224x over previous
#include <cuda_runtime.h>
#include <cuda_fp16.h>
#include <math.h>

#define NN   1024
#define HH   128
#define DD   256
#define NLVL 3
#define LN_EPS 1e-5f

// -------- device scratch (static: allocation-free kernel_launch) --------
__device__ float g_x[NN*HH];
__device__ float g_pre[NN*HH];
__device__ float g_prj[NN*HH];
__device__ float g_msum[NN*HH];
__device__ float g_lmean[NLVL*HH];
__device__ __half g_ew[(long long)NN*NN*HH];  // 256 MB fp16, level-invariant

// proven-accurate silu (R4: rel_err 3.5e-6)
__device__ __forceinline__ float silu_f(float x) {
    return __fdividef(x, 1.f + __expf(-x));
}

__device__ __forceinline__ float warp_sum(float v) {
    #pragma unroll
    for (int off = 16; off; off >>= 1)
        v += __shfl_xor_sync(0xffffffffu, v, off);
    return v;
}

// ---------------------------------------------------------------
__global__ void k_init(const int* __restrict__ an, const float* __restrict__ emb) {
    int t = blockIdx.x * blockDim.x + threadIdx.x;
    if (t < NLVL*HH) g_lmean[t] = 0.f;
    int n = t >> 7;
    int h = t & 127;
    g_x[t] = emb[an[n]*HH + h];
}

// ---------------------------------------------------------------
// ew[i,j,:] = LN(silu(scales(i,j) @ de_W + de_b)) * de_g + de_be   (fp16 out)
// symmetric: compute j>=i, write both mirrors. warp per (i,j).
__global__ void __launch_bounds__(256) k_ew(
    const float* __restrict__ pos,
    const float* __restrict__ deW, const float* __restrict__ deb,
    const float* __restrict__ deg, const float* __restrict__ debe)
{
    int warp = threadIdx.x >> 5;
    int lane = threadIdx.x & 31;
    int i = blockIdx.y;
    int j = (blockIdx.x << 3) + warp;
    if (j < i) return;

    float dx = pos[3*i]   - pos[3*j];
    float dy = pos[3*i+1] - pos[3*j+1];
    float dz = pos[3*i+2] - pos[3*j+2];
    float sq = dx*dx + dy*dy + dz*dz;
    float d  = (sq > 0.f) ? sqrtf(sq) : 0.f;
    float s3 = __expf(-0.25f * d);
    float s2 = s3 * s3;
    float s1 = s2 * s2;

    int h0 = lane << 2;
    float4 w0 = *(const float4*)(deW + h0);
    float4 w1 = *(const float4*)(deW + HH + h0);
    float4 w2 = *(const float4*)(deW + 2*HH + h0);
    float4 bb = *(const float4*)(deb + h0);

    float v0 = fmaf(s1, w0.x, fmaf(s2, w1.x, fmaf(s3, w2.x, bb.x)));
    float v1 = fmaf(s1, w0.y, fmaf(s2, w1.y, fmaf(s3, w2.y, bb.y)));
    float v2 = fmaf(s1, w0.z, fmaf(s2, w1.z, fmaf(s3, w2.z, bb.z)));
    float v3 = fmaf(s1, w0.w, fmaf(s2, w1.w, fmaf(s3, w2.w, bb.w)));

    v0 = silu_f(v0); v1 = silu_f(v1); v2 = silu_f(v2); v3 = silu_f(v3);

    float p = warp_sum(v0 + v1 + v2 + v3);
    float q = warp_sum(fmaf(v0,v0, fmaf(v1,v1, fmaf(v2,v2, v3*v3))));
    float mu   = p * (1.f/HH);
    float var  = fmaf(-mu, mu, q * (1.f/HH));
    float rstd = rsqrtf(var + LN_EPS);

    float4 gg = *(const float4*)(deg + h0);
    float4 be = *(const float4*)(debe + h0);
    float o0 = fmaf((v0 - mu) * rstd, gg.x, be.x);
    float o1 = fmaf((v1 - mu) * rstd, gg.y, be.y);
    float o2 = fmaf((v2 - mu) * rstd, gg.z, be.z);
    float o3 = fmaf((v3 - mu) * rstd, gg.w, be.w);

    __half2 ha = __floats2half2_rn(o0, o1);
    __half2 hb = __floats2half2_rn(o2, o3);
    float2 pack = make_float2(__uint_as_float(*(unsigned*)&ha),
                              __uint_as_float(*(unsigned*)&hb));
    // streaming stores: written once, read once next kernel
    __stcs((float2*)(g_ew + ((long long)i*NN + j)*HH + h0), pack);
    if (j != i)
        __stcs((float2*)(g_ew + ((long long)j*NN + i)*HH + h0), pack);
}

// ---------------------------------------------------------------
// pre = x@Wi + msg_b, prj = x@Wj.  8 nodes/block, 128 threads (h).
__global__ void __launch_bounds__(128) k_preprj(
    const float* __restrict__ msgW, const float* __restrict__ msgb, int lvl)
{
    __shared__ float xs[8][HH];
    int h  = threadIdx.x;
    int n0 = blockIdx.x << 3;
    #pragma unroll
    for (int nn = 0; nn < 8; nn++) xs[nn][h] = g_x[(n0+nn)*HH + h];
    __syncthreads();

    const float* Wi = msgW + (size_t)lvl*2*HH*HH;
    const float* Wj = Wi + HH*HH;
    float ai[8], aj[8];
    #pragma unroll
    for (int nn = 0; nn < 8; nn++) { ai[nn] = 0.f; aj[nn] = 0.f; }

    for (int k = 0; k < HH; k++) {
        float wi = Wi[k*HH + h];
        float wj = Wj[k*HH + h];
        #pragma unroll
        for (int nn = 0; nn < 8; nn++) {
            ai[nn] = fmaf(xs[nn][k], wi, ai[nn]);
            aj[nn] = fmaf(xs[nn][k], wj, aj[nn]);
        }
    }
    float bb = msgb[lvl*HH + h];
    #pragma unroll
    for (int nn = 0; nn < 8; nn++) {
        g_pre[(n0+nn)*HH + h] = ai[nn] + bb;
        g_prj[(n0+nn)*HH + h] = aj[nn];
    }
}

// ---------------------------------------------------------------
// msum[i,h] = sum_j LN(silu(pre_i + prj_j))_h * ew[i,j,h]
// block per i, 8 warps; j-loop unrolled 4x for ILP (8 independent
// shuffle chains in flight -> hides SHFL latency that bound R4).
__global__ void __launch_bounds__(256) k_msum(
    const float* __restrict__ msgg, const float* __restrict__ msgbe, int lvl)
{
    __shared__ float red[8][HH];
    int i    = blockIdx.x;
    int warp = threadIdx.x >> 5;
    int lane = threadIdx.x & 31;
    int h0   = lane << 2;

    float4 pre4 = *(const float4*)(g_pre + i*HH + h0);
    float4 gg   = *(const float4*)(msgg  + lvl*HH + h0);
    float4 bb   = *(const float4*)(msgbe + lvl*HH + h0);

    float a0 = 0.f, a1 = 0.f, a2 = 0.f, a3 = 0.f;
    const float2* ewrow = (const float2*)(g_ew + (long long)i*NN*HH + h0);

    #pragma unroll 4
    for (int jj = 0; jj < NN/8; jj++) {
        int j = warp + (jj << 3);
        float4 pj = *(const float4*)(g_prj + j*HH + h0);
        // streaming 8B load of 4 halves; row stride = HH halves = HH/4 float2
        float2 epk = __ldcs(ewrow + (long long)j*(HH/4));

        float s0 = silu_f(pre4.x + pj.x);
        float s1 = silu_f(pre4.y + pj.y);
        float s2 = silu_f(pre4.z + pj.z);
        float s3 = silu_f(pre4.w + pj.w);

        float p = warp_sum(s0 + s1 + s2 + s3);
        float q = warp_sum(fmaf(s0,s0, fmaf(s1,s1, fmaf(s2,s2, s3*s3))));
        float mu   = p * (1.f/HH);
        float var  = fmaf(-mu, mu, q * (1.f/HH));
        float rstd = rsqrtf(var + LN_EPS);
        float c0   = -mu * rstd;   // s*rstd + c0 == (s-mu)*rstd

        unsigned ua = __float_as_uint(epk.x), ub = __float_as_uint(epk.y);
        float2 e01 = __half22float2(*(__half2*)&ua);
        float2 e23 = __half22float2(*(__half2*)&ub);

        a0 = fmaf(fmaf(fmaf(s0, rstd, c0), gg.x, bb.x), e01.x, a0);
        a1 = fmaf(fmaf(fmaf(s1, rstd, c0), gg.y, bb.y), e01.y, a1);
        a2 = fmaf(fmaf(fmaf(s2, rstd, c0), gg.z, bb.z), e23.x, a2);
        a3 = fmaf(fmaf(fmaf(s3, rstd, c0), gg.w, bb.w), e23.y, a3);
    }

    red[warp][h0+0] = a0; red[warp][h0+1] = a1;
    red[warp][h0+2] = a2; red[warp][h0+3] = a3;
    __syncthreads();
    if (threadIdx.x < HH) {
        int h = threadIdx.x;
        float s = 0.f;
        #pragma unroll
        for (int w = 0; w < 8; w++) s += red[w][h];
        g_msum[i*HH + h] = s;
    }
}

// ---------------------------------------------------------------
// x += LN(silu([x, msum] @ upd_W + upd_b)); accumulate level mean.
__global__ void __launch_bounds__(128) k_upd(
    const float* __restrict__ updW, const float* __restrict__ updb,
    const float* __restrict__ updg, const float* __restrict__ updbe, int lvl)
{
    __shared__ float us[2*HH];
    __shared__ float rp[4], rq[4];
    __shared__ float s_mu, s_rstd;
    int i = blockIdx.x;
    int h = threadIdx.x;
    int warp = h >> 5, lane = h & 31;

    us[h]      = g_x[i*HH + h];
    us[HH + h] = g_msum[i*HH + h];
    __syncthreads();

    const float* W = updW + (size_t)lvl*2*HH*HH;
    float acc = updb[lvl*HH + h];
    #pragma unroll 4
    for (int k = 0; k < 2*HH; k++) acc = fmaf(us[k], W[k*HH + h], acc);

    float s = silu_f(acc);

    float p = warp_sum(s);
    float q = warp_sum(s*s);
    if (lane == 0) { rp[warp] = p; rq[warp] = q; }
    __syncthreads();
    if (h == 0) {
        float P = rp[0]+rp[1]+rp[2]+rp[3];
        float Q = rq[0]+rq[1]+rq[2]+rq[3];
        float mu = P * (1.f/HH);
        s_mu = mu;
        s_rstd = rsqrtf(fmaf(-mu, mu, Q * (1.f/HH)) + LN_EPS);
    }
    __syncthreads();

    float m  = fmaf((s - s_mu) * s_rstd, updg[lvl*HH + h], updbe[lvl*HH + h]);
    float xn = us[h] + m;
    g_x[i*HH + h] = xn;
    atomicAdd(&g_lmean[lvl*HH + h], xn * (1.f/NN));
}

// ---------------------------------------------------------------
__global__ void __launch_bounds__(256) k_final(
    const float* __restrict__ fpW, const float* __restrict__ fpb,
    const float* __restrict__ fpg, const float* __restrict__ fpbe,
    float* __restrict__ out)
{
    __shared__ float cs[NLVL*HH];
    __shared__ float rp[8], rq[8];
    __shared__ float s_mu, s_rstd;
    int t = threadIdx.x;
    int warp = t >> 5, lane = t & 31;

    for (int k = t; k < NLVL*HH; k += 256) cs[k] = g_lmean[k];
    __syncthreads();

    float acc = fpb[t];
    #pragma unroll 4
    for (int k = 0; k < NLVL*HH; k++) acc = fmaf(cs[k], fpW[k*DD + t], acc);

    float p = warp_sum(acc);
    float q = warp_sum(acc*acc);
    if (lane == 0) { rp[warp] = p; rq[warp] = q; }
    __syncthreads();
    if (t == 0) {
        float P = 0.f, Q = 0.f;
        #pragma unroll
        for (int w = 0; w < 8; w++) { P += rp[w]; Q += rq[w]; }
        float mu = P * (1.f/DD);
        s_mu = mu;
        s_rstd = rsqrtf(fmaf(-mu, mu, Q * (1.f/DD)) + LN_EPS);
    }
    __syncthreads();

    out[t] = fmaf((acc - s_mu) * s_rstd, fpg[t], fpbe[t]);
}

// ---------------------------------------------------------------
extern "C" void kernel_launch(void* const* d_in, const int* in_sizes, int n_in,
                              void* d_out, int out_size) {
    const int*   an    = (const int*)  d_in[0];
    const float* pos   = (const float*)d_in[1];
    const float* emb   = (const float*)d_in[2];
    const float* deW   = (const float*)d_in[3];
    const float* deb   = (const float*)d_in[4];
    const float* deg   = (const float*)d_in[5];
    const float* debe  = (const float*)d_in[6];
    const float* msgW  = (const float*)d_in[7];
    const float* msgb  = (const float*)d_in[8];
    const float* msgg  = (const float*)d_in[9];
    const float* msgbe = (const float*)d_in[10];
    const float* updW  = (const float*)d_in[11];
    const float* updb  = (const float*)d_in[12];
    const float* updg  = (const float*)d_in[13];
    const float* updbe = (const float*)d_in[14];
    const float* fpW   = (const float*)d_in[15];
    const float* fpb   = (const float*)d_in[16];
    const float* fpg   = (const float*)d_in[17];
    const float* fpbe  = (const float*)d_in[18];
    float* out = (float*)d_out;

    k_init<<<512, 256>>>(an, emb);
    k_ew<<<dim3(128, 1024), 256>>>(pos, deW, deb, deg, debe);
    for (int lvl = 0; lvl < NLVL; lvl++) {
        k_preprj<<<128, 128>>>(msgW, msgb, lvl);
        k_msum<<<1024, 256>>>(msgg, msgbe, lvl);
        k_upd<<<1024, 128>>>(updW, updb, updg, updbe, lvl);
    }
    k_final<<<1, 256>>>(fpW, fpb, fpg, fpbe, out);
}

// round 8
// speedup vs baseline: 1.9269x; 1.1188x over previous
#include <cuda_runtime.h>
#include <cuda_fp16.h>
#include <math.h>

#define NN   1024
#define HH   128
#define DD   256
#define NLVL 3
#define LN_EPS 1e-5f

// -------- device scratch (static: allocation-free kernel_launch) --------
__device__ float g_x[NN*HH];
__device__ float g_pre[NN*HH];
__device__ float g_prj[NN*HH];
__device__ float g_msum[NN*HH];
__device__ float g_esum[NN*HH];     // sum_j ew[i,j,h]  (level-invariant)
__device__ float g_lmean[NLVL*HH];
__device__ __half g_ew[(long long)NN*NN*HH];  // 256 MB fp16, level-invariant

// 1-MUFU silu: silu(x) = 0.5*x*(1 + tanh(0.5*x))
__device__ __forceinline__ float silu_f(float x) {
    float t;
    asm("tanh.approx.f32 %0, %1;" : "=f"(t) : "f"(x * 0.5f));
    float hx = 0.5f * x;
    return fmaf(hx, t, hx);
}

__device__ __forceinline__ float warp_sum(float v) {
    #pragma unroll
    for (int off = 16; off; off >>= 1)
        v += __shfl_xor_sync(0xffffffffu, v, off);
    return v;
}

// ---------------------------------------------------------------
__global__ void k_init(const int* __restrict__ an, const float* __restrict__ emb) {
    int t = blockIdx.x * blockDim.x + threadIdx.x;
    if (t < NLVL*HH) g_lmean[t] = 0.f;
    int n = t >> 7;
    int h = t & 127;
    g_x[t] = emb[an[n]*HH + h];
}

// ---------------------------------------------------------------
// ew[i,j,:] = LN(silu(scales(i,j) @ de_W + de_b)) * de_g + de_be   (fp16 out)
// symmetric: compute j>=i, write both mirrors. warp per (i,j).
__global__ void __launch_bounds__(256) k_ew(
    const float* __restrict__ pos,
    const float* __restrict__ deW, const float* __restrict__ deb,
    const float* __restrict__ deg, const float* __restrict__ debe)
{
    int warp = threadIdx.x >> 5;
    int lane = threadIdx.x & 31;
    int i = blockIdx.y;
    int j = (blockIdx.x << 3) + warp;
    if (j < i) return;

    float dx = pos[3*i]   - pos[3*j];
    float dy = pos[3*i+1] - pos[3*j+1];
    float dz = pos[3*i+2] - pos[3*j+2];
    float sq = dx*dx + dy*dy + dz*dz;
    float d  = (sq > 0.f) ? sqrtf(sq) : 0.f;
    float s3 = __expf(-0.25f * d);
    float s2 = s3 * s3;
    float s1 = s2 * s2;

    int h0 = lane << 2;
    float4 w0 = *(const float4*)(deW + h0);
    float4 w1 = *(const float4*)(deW + HH + h0);
    float4 w2 = *(const float4*)(deW + 2*HH + h0);
    float4 bb = *(const float4*)(deb + h0);

    float v0 = fmaf(s1, w0.x, fmaf(s2, w1.x, fmaf(s3, w2.x, bb.x)));
    float v1 = fmaf(s1, w0.y, fmaf(s2, w1.y, fmaf(s3, w2.y, bb.y)));
    float v2 = fmaf(s1, w0.z, fmaf(s2, w1.z, fmaf(s3, w2.z, bb.z)));
    float v3 = fmaf(s1, w0.w, fmaf(s2, w1.w, fmaf(s3, w2.w, bb.w)));

    v0 = silu_f(v0); v1 = silu_f(v1); v2 = silu_f(v2); v3 = silu_f(v3);

    float p = warp_sum(v0 + v1 + v2 + v3);
    float q = warp_sum(fmaf(v0,v0, fmaf(v1,v1, fmaf(v2,v2, v3*v3))));
    float mu   = p * (1.f/HH);
    float var  = fmaf(-mu, mu, q * (1.f/HH));
    float rstd = rsqrtf(var + LN_EPS);

    float4 gg = *(const float4*)(deg + h0);
    float4 be = *(const float4*)(debe + h0);
    float o0 = fmaf((v0 - mu) * rstd, gg.x, be.x);
    float o1 = fmaf((v1 - mu) * rstd, gg.y, be.y);
    float o2 = fmaf((v2 - mu) * rstd, gg.z, be.z);
    float o3 = fmaf((v3 - mu) * rstd, gg.w, be.w);

    __half2 ha = __floats2half2_rn(o0, o1);
    __half2 hb = __floats2half2_rn(o2, o3);
    float2 pack = make_float2(__uint_as_float(*(unsigned*)&ha),
                              __uint_as_float(*(unsigned*)&hb));
    __stcs((float2*)(g_ew + ((long long)i*NN + j)*HH + h0), pack);
    if (j != i)
        __stcs((float2*)(g_ew + ((long long)j*NN + i)*HH + h0), pack);
}

// ---------------------------------------------------------------
// pre = x@Wi + msg_b, prj = x@Wj.  8 nodes/block, 128 threads (h).
__global__ void __launch_bounds__(128) k_preprj(
    const float* __restrict__ msgW, const float* __restrict__ msgb, int lvl)
{
    __shared__ float xs[8][HH];
    int h  = threadIdx.x;
    int n0 = blockIdx.x << 3;
    #pragma unroll
    for (int nn = 0; nn < 8; nn++) xs[nn][h] = g_x[(n0+nn)*HH + h];
    __syncthreads();

    const float* Wi = msgW + (size_t)lvl*2*HH*HH;
    const float* Wj = Wi + HH*HH;
    float ai[8], aj[8];
    #pragma unroll
    for (int nn = 0; nn < 8; nn++) { ai[nn] = 0.f; aj[nn] = 0.f; }

    for (int k = 0; k < HH; k++) {
        float wi = Wi[k*HH + h];
        float wj = Wj[k*HH + h];
        #pragma unroll
        for (int nn = 0; nn < 8; nn++) {
            ai[nn] = fmaf(xs[nn][k], wi, ai[nn]);
            aj[nn] = fmaf(xs[nn][k], wj, aj[nn]);
        }
    }
    float bb = msgb[lvl*HH + h];
    #pragma unroll
    for (int nn = 0; nn < 8; nn++) {
        g_pre[(n0+nn)*HH + h] = ai[nn] + bb;
        g_prj[(n0+nn)*HH + h] = aj[nn];
    }
}

// ---------------------------------------------------------------
// msum[i,h] = g[h]*sum_j (s-mu)*rstd*e  +  be[h]*sum_j e
// The second sum is level-invariant: computed at level 0 into g_esum.
// block per i, 8 warps, j-loop unrolled 4x for ILP.
template<bool FIRST>
__global__ void __launch_bounds__(256) k_msum(
    const float* __restrict__ msgg, const float* __restrict__ msgbe, int lvl)
{
    __shared__ float red[8][HH];
    __shared__ float red2[8][HH];
    int i    = blockIdx.x;
    int warp = threadIdx.x >> 5;
    int lane = threadIdx.x & 31;
    int h0   = lane << 2;

    float4 pre4 = *(const float4*)(g_pre + i*HH + h0);

    float a0 = 0.f, a1 = 0.f, a2 = 0.f, a3 = 0.f;
    float z0 = 0.f, z1 = 0.f, z2 = 0.f, z3 = 0.f;   // e-sums (FIRST only)
    const float2* ewrow = (const float2*)(g_ew + (long long)i*NN*HH + h0);

    #pragma unroll 4
    for (int jj = 0; jj < NN/8; jj++) {
        int j = warp + (jj << 3);
        float4 pj = *(const float4*)(g_prj + j*HH + h0);
        float2 epk = __ldcs(ewrow + (long long)j*(HH/4));

        float s0 = silu_f(pre4.x + pj.x);
        float s1 = silu_f(pre4.y + pj.y);
        float s2 = silu_f(pre4.z + pj.z);
        float s3 = silu_f(pre4.w + pj.w);

        float p = warp_sum(s0 + s1 + s2 + s3);
        float q = warp_sum(fmaf(s0,s0, fmaf(s1,s1, fmaf(s2,s2, s3*s3))));
        float mu   = p * (1.f/HH);
        float var  = fmaf(-mu, mu, q * (1.f/HH));
        float rstd = rsqrtf(var + LN_EPS);
        float c0   = -mu * rstd;

        unsigned ua = __float_as_uint(epk.x), ub = __float_as_uint(epk.y);
        float2 e01 = __half22float2(*(__half2*)&ua);
        float2 e23 = __half22float2(*(__half2*)&ub);

        a0 = fmaf(fmaf(s0, rstd, c0), e01.x, a0);
        a1 = fmaf(fmaf(s1, rstd, c0), e01.y, a1);
        a2 = fmaf(fmaf(s2, rstd, c0), e23.x, a2);
        a3 = fmaf(fmaf(s3, rstd, c0), e23.y, a3);
        if (FIRST) {
            z0 += e01.x; z1 += e01.y; z2 += e23.x; z3 += e23.y;
        }
    }

    red[warp][h0+0] = a0; red[warp][h0+1] = a1;
    red[warp][h0+2] = a2; red[warp][h0+3] = a3;
    if (FIRST) {
        red2[warp][h0+0] = z0; red2[warp][h0+1] = z1;
        red2[warp][h0+2] = z2; red2[warp][h0+3] = z3;
    }
    __syncthreads();
    if (threadIdx.x < HH) {
        int h = threadIdx.x;
        float S1 = 0.f, S0 = 0.f;
        #pragma unroll
        for (int w = 0; w < 8; w++) S1 += red[w][h];
        if (FIRST) {
            #pragma unroll
            for (int w = 0; w < 8; w++) S0 += red2[w][h];
            g_esum[i*HH + h] = S0;
        } else {
            S0 = g_esum[i*HH + h];
        }
        g_msum[i*HH + h] = fmaf(msgg[lvl*HH + h], S1, msgbe[lvl*HH + h] * S0);
    }
}

// ---------------------------------------------------------------
// x += LN(silu([x, msum] @ upd_W + upd_b)); accumulate level mean.
__global__ void __launch_bounds__(128) k_upd(
    const float* __restrict__ updW, const float* __restrict__ updb,
    const float* __restrict__ updg, const float* __restrict__ updbe, int lvl)
{
    __shared__ float us[2*HH];
    __shared__ float rp[4], rq[4];
    __shared__ float s_mu, s_rstd;
    int i = blockIdx.x;
    int h = threadIdx.x;
    int warp = h >> 5, lane = h & 31;

    us[h]      = g_x[i*HH + h];
    us[HH + h] = g_msum[i*HH + h];
    __syncthreads();

    const float* W = updW + (size_t)lvl*2*HH*HH;
    float acc = updb[lvl*HH + h];
    #pragma unroll 4
    for (int k = 0; k < 2*HH; k++) acc = fmaf(us[k], W[k*HH + h], acc);

    float s = silu_f(acc);

    float p = warp_sum(s);
    float q = warp_sum(s*s);
    if (lane == 0) { rp[warp] = p; rq[warp] = q; }
    __syncthreads();
    if (h == 0) {
        float P = rp[0]+rp[1]+rp[2]+rp[3];
        float Q = rq[0]+rq[1]+rq[2]+rq[3];
        float mu = P * (1.f/HH);
        s_mu = mu;
        s_rstd = rsqrtf(fmaf(-mu, mu, Q * (1.f/HH)) + LN_EPS);
    }
    __syncthreads();

    float m  = fmaf((s - s_mu) * s_rstd, updg[lvl*HH + h], updbe[lvl*HH + h]);
    float xn = us[h] + m;
    g_x[i*HH + h] = xn;
    atomicAdd(&g_lmean[lvl*HH + h], xn * (1.f/NN));
}

// ---------------------------------------------------------------
__global__ void __launch_bounds__(256) k_final(
    const float* __restrict__ fpW, const float* __restrict__ fpb,
    const float* __restrict__ fpg, const float* __restrict__ fpbe,
    float* __restrict__ out)
{
    __shared__ float cs[NLVL*HH];
    __shared__ float rp[8], rq[8];
    __shared__ float s_mu, s_rstd;
    int t = threadIdx.x;
    int warp = t >> 5, lane = t & 31;

    for (int k = t; k < NLVL*HH; k += 256) cs[k] = g_lmean[k];
    __syncthreads();

    float acc = fpb[t];
    #pragma unroll 4
    for (int k = 0; k < NLVL*HH; k++) acc = fmaf(cs[k], fpW[k*DD + t], acc);

    float p = warp_sum(acc);
    float q = warp_sum(acc*acc);
    if (lane == 0) { rp[warp] = p; rq[warp] = q; }
    __syncthreads();
    if (t == 0) {
        float P = 0.f, Q = 0.f;
        #pragma unroll
        for (int w = 0; w < 8; w++) { P += rp[w]; Q += rq[w]; }
        float mu = P * (1.f/DD);
        s_mu = mu;
        s_rstd = rsqrtf(fmaf(-mu, mu, Q * (1.f/DD)) + LN_EPS);
    }
    __syncthreads();

    out[t] = fmaf((acc - s_mu) * s_rstd, fpg[t], fpbe[t]);
}

// ---------------------------------------------------------------
extern "C" void kernel_launch(void* const* d_in, const int* in_sizes, int n_in,
                              void* d_out, int out_size) {
    const int*   an    = (const int*)  d_in[0];
    const float* pos   = (const float*)d_in[1];
    const float* emb   = (const float*)d_in[2];
    const float* deW   = (const float*)d_in[3];
    const float* deb   = (const float*)d_in[4];
    const float* deg   = (const float*)d_in[5];
    const float* debe  = (const float*)d_in[6];
    const float* msgW  = (const float*)d_in[7];
    const float* msgb  = (const float*)d_in[8];
    const float* msgg  = (const float*)d_in[9];
    const float* msgbe = (const float*)d_in[10];
    const float* updW  = (const float*)d_in[11];
    const float* updb  = (const float*)d_in[12];
    const float* updg  = (const float*)d_in[13];
    const float* updbe = (const float*)d_in[14];
    const float* fpW   = (const float*)d_in[15];
    const float* fpb   = (const float*)d_in[16];
    const float* fpg   = (const float*)d_in[17];
    const float* fpbe  = (const float*)d_in[18];
    float* out = (float*)d_out;

    k_init<<<512, 256>>>(an, emb);
    k_ew<<<dim3(128, 1024), 256>>>(pos, deW, deb, deg, debe);
    for (int lvl = 0; lvl < NLVL; lvl++) {
        k_preprj<<<128, 128>>>(msgW, msgb, lvl);
        if (lvl == 0) k_msum<true><<<1024, 256>>>(msgg, msgbe, lvl);
        else          k_msum<false><<<1024, 256>>>(msgg, msgbe, lvl);
        k_upd<<<1024, 128>>>(updW, updb, updg, updbe, lvl);
    }
    k_final<<<1, 256>>>(fpW, fpb, fpg, fpbe, out);
}

// round 9
// speedup vs baseline: 2.1225x; 1.1015x over previous
#include <cuda_runtime.h>
#include <cuda_fp16.h>
#include <math.h>

#define NN   1024
#define HH   128
#define DD   256
#define NLVL 3
#define LN_EPS 1e-5f

// -------- device scratch (static: allocation-free kernel_launch) --------
__device__ float g_x[NN*HH];
__device__ float g_pre[NN*HH];
__device__ float g_prj[NN*HH];
__device__ float g_msum[NN*HH];
__device__ float g_esum[NN*HH];     // sum_j ew[i,j,h]  (level-invariant)
__device__ float g_lmean[NLVL*HH];
__device__ __half g_ew[(long long)NN*NN*HH];  // 256 MB fp16, level-invariant

// 1-MUFU silu: silu(x) = 0.5*x*(1 + tanh(0.5*x))
__device__ __forceinline__ float silu_f(float x) {
    float t;
    asm("tanh.approx.f32 %0, %1;" : "=f"(t) : "f"(x * 0.5f));
    float hx = 0.5f * x;
    return fmaf(hx, t, hx);
}

__device__ __forceinline__ float warp_sum(float v) {
    #pragma unroll
    for (int off = 16; off; off >>= 1)
        v += __shfl_xor_sync(0xffffffffu, v, off);
    return v;
}

// ---------------------------------------------------------------
__global__ void k_init(const int* __restrict__ an, const float* __restrict__ emb) {
    int t = blockIdx.x * blockDim.x + threadIdx.x;
    if (t < NLVL*HH) g_lmean[t] = 0.f;
    int n = t >> 7;
    int h = t & 127;
    g_x[t] = emb[an[n]*HH + h];
}

// ---------------------------------------------------------------
// ew[i,j,:] = LN(silu(scales(i,j) @ de_W + de_b)) * de_g + de_be   (fp16 out)
// symmetric: compute j>=i, write both mirrors. warp per (i,j).
__global__ void __launch_bounds__(256) k_ew(
    const float* __restrict__ pos,
    const float* __restrict__ deW, const float* __restrict__ deb,
    const float* __restrict__ deg, const float* __restrict__ debe)
{
    int warp = threadIdx.x >> 5;
    int lane = threadIdx.x & 31;
    int i = blockIdx.y;
    int j = (blockIdx.x << 3) + warp;
    if (j < i) return;

    float dx = pos[3*i]   - pos[3*j];
    float dy = pos[3*i+1] - pos[3*j+1];
    float dz = pos[3*i+2] - pos[3*j+2];
    float sq = dx*dx + dy*dy + dz*dz;
    float d  = (sq > 0.f) ? sqrtf(sq) : 0.f;
    float s3 = __expf(-0.25f * d);
    float s2 = s3 * s3;
    float s1 = s2 * s2;

    int h0 = lane << 2;
    float4 w0 = *(const float4*)(deW + h0);
    float4 w1 = *(const float4*)(deW + HH + h0);
    float4 w2 = *(const float4*)(deW + 2*HH + h0);
    float4 bb = *(const float4*)(deb + h0);

    float v0 = fmaf(s1, w0.x, fmaf(s2, w1.x, fmaf(s3, w2.x, bb.x)));
    float v1 = fmaf(s1, w0.y, fmaf(s2, w1.y, fmaf(s3, w2.y, bb.y)));
    float v2 = fmaf(s1, w0.z, fmaf(s2, w1.z, fmaf(s3, w2.z, bb.z)));
    float v3 = fmaf(s1, w0.w, fmaf(s2, w1.w, fmaf(s3, w2.w, bb.w)));

    v0 = silu_f(v0); v1 = silu_f(v1); v2 = silu_f(v2); v3 = silu_f(v3);

    float p = warp_sum(v0 + v1 + v2 + v3);
    float q = warp_sum(fmaf(v0,v0, fmaf(v1,v1, fmaf(v2,v2, v3*v3))));
    float mu   = p * (1.f/HH);
    float var  = fmaf(-mu, mu, q * (1.f/HH));
    float rstd = rsqrtf(var + LN_EPS);

    float4 gg = *(const float4*)(deg + h0);
    float4 be = *(const float4*)(debe + h0);
    float o0 = fmaf((v0 - mu) * rstd, gg.x, be.x);
    float o1 = fmaf((v1 - mu) * rstd, gg.y, be.y);
    float o2 = fmaf((v2 - mu) * rstd, gg.z, be.z);
    float o3 = fmaf((v3 - mu) * rstd, gg.w, be.w);

    __half2 ha = __floats2half2_rn(o0, o1);
    __half2 hb = __floats2half2_rn(o2, o3);
    float2 pack = make_float2(__uint_as_float(*(unsigned*)&ha),
                              __uint_as_float(*(unsigned*)&hb));
    __stcs((float2*)(g_ew + ((long long)i*NN + j)*HH + h0), pack);
    if (j != i)
        __stcs((float2*)(g_ew + ((long long)j*NN + i)*HH + h0), pack);
}

// ---------------------------------------------------------------
// pre = x@Wi + msg_b, prj = x@Wj.  8 nodes/block, 128 threads (h).
__global__ void __launch_bounds__(128) k_preprj(
    const float* __restrict__ msgW, const float* __restrict__ msgb, int lvl)
{
    __shared__ float xs[8][HH];
    int h  = threadIdx.x;
    int n0 = blockIdx.x << 3;
    #pragma unroll
    for (int nn = 0; nn < 8; nn++) xs[nn][h] = g_x[(n0+nn)*HH + h];
    __syncthreads();

    const float* Wi = msgW + (size_t)lvl*2*HH*HH;
    const float* Wj = Wi + HH*HH;
    float ai[8], aj[8];
    #pragma unroll
    for (int nn = 0; nn < 8; nn++) { ai[nn] = 0.f; aj[nn] = 0.f; }

    for (int k = 0; k < HH; k++) {
        float wi = Wi[k*HH + h];
        float wj = Wj[k*HH + h];
        #pragma unroll
        for (int nn = 0; nn < 8; nn++) {
            ai[nn] = fmaf(xs[nn][k], wi, ai[nn]);
            aj[nn] = fmaf(xs[nn][k], wj, aj[nn]);
        }
    }
    float bb = msgb[lvl*HH + h];
    #pragma unroll
    for (int nn = 0; nn < 8; nn++) {
        g_pre[(n0+nn)*HH + h] = ai[nn] + bb;
        g_prj[(n0+nn)*HH + h] = aj[nn];
    }
}

// ---------------------------------------------------------------
// msum[i,h] = g[h]*sum_j (s-mu)*rstd*e  +  be[h]*sum_j e
// Lane repartition: 16 lanes per j (8 h each), 2 j per warp.
// LN butterfly: 4 steps within 16-lane groups (SHFL per j: 10 -> 4).
template<bool FIRST>
__global__ void __launch_bounds__(256) k_msum(
    const float* __restrict__ msgg, const float* __restrict__ msgbe, int lvl)
{
    __shared__ float red[16][HH];
    __shared__ float red2[16][HH];   // only used when FIRST
    int i    = blockIdx.x;
    int warp = threadIdx.x >> 5;
    int lane = threadIdx.x & 31;
    int grp  = lane >> 4;            // 0/1: which j of the pair
    int l16  = lane & 15;
    int h0   = l16 << 3;             // 8 h per lane

    float pre[8];
    *(float4*)(pre)     = *(const float4*)(g_pre + i*HH + h0);
    *(float4*)(pre + 4) = *(const float4*)(g_pre + i*HH + h0 + 4);

    float a[8] = {0,0,0,0,0,0,0,0};
    float z[8] = {0,0,0,0,0,0,0,0};

    const __half* ewbase = g_ew + (long long)i*NN*HH + h0;
    int jfix = (warp << 1) + grp;

    #pragma unroll 2
    for (int jj = 0; jj < NN/16; jj++) {
        int j = (jj << 4) + jfix;
        float4 pja = *(const float4*)(g_prj + j*HH + h0);
        float4 pjb = *(const float4*)(g_prj + j*HH + h0 + 4);
        uint4  epk = __ldcs((const uint4*)(ewbase + (long long)j*HH));

        float s[8];
        s[0] = silu_f(pre[0] + pja.x);
        s[1] = silu_f(pre[1] + pja.y);
        s[2] = silu_f(pre[2] + pja.z);
        s[3] = silu_f(pre[3] + pja.w);
        s[4] = silu_f(pre[4] + pjb.x);
        s[5] = silu_f(pre[5] + pjb.y);
        s[6] = silu_f(pre[6] + pjb.z);
        s[7] = silu_f(pre[7] + pjb.w);

        float p = ((s[0]+s[1])+(s[2]+s[3])) + ((s[4]+s[5])+(s[6]+s[7]));
        float q = fmaf(s[0],s[0], fmaf(s[1],s[1], fmaf(s[2],s[2], s[3]*s[3])))
                + fmaf(s[4],s[4], fmaf(s[5],s[5], fmaf(s[6],s[6], s[7]*s[7])));
        #pragma unroll
        for (int off = 8; off; off >>= 1) {
            p += __shfl_xor_sync(0xffffffffu, p, off);
            q += __shfl_xor_sync(0xffffffffu, q, off);
        }
        float mu   = p * (1.f/HH);
        float var  = fmaf(-mu, mu, q * (1.f/HH));
        float rstd = rsqrtf(var + LN_EPS);
        float c0   = -mu * rstd;

        unsigned u0 = epk.x, u1 = epk.y, u2 = epk.z, u3 = epk.w;
        float2 f0 = __half22float2(*(__half2*)&u0);
        float2 f1 = __half22float2(*(__half2*)&u1);
        float2 f2 = __half22float2(*(__half2*)&u2);
        float2 f3 = __half22float2(*(__half2*)&u3);
        float e[8] = { f0.x, f0.y, f1.x, f1.y, f2.x, f2.y, f3.x, f3.y };

        #pragma unroll
        for (int k = 0; k < 8; k++) {
            a[k] = fmaf(fmaf(s[k], rstd, c0), e[k], a[k]);
            if (FIRST) z[k] += e[k];
        }
    }

    int slot = (warp << 1) | grp;
    #pragma unroll
    for (int k = 0; k < 8; k++) red[slot][h0+k] = a[k];
    if (FIRST) {
        #pragma unroll
        for (int k = 0; k < 8; k++) red2[slot][h0+k] = z[k];
    }
    __syncthreads();
    if (threadIdx.x < HH) {
        int h = threadIdx.x;
        float S1 = 0.f, S0 = 0.f;
        #pragma unroll
        for (int w = 0; w < 16; w++) S1 += red[w][h];
        if (FIRST) {
            #pragma unroll
            for (int w = 0; w < 16; w++) S0 += red2[w][h];
            g_esum[i*HH + h] = S0;
        } else {
            S0 = g_esum[i*HH + h];
        }
        g_msum[i*HH + h] = fmaf(msgg[lvl*HH + h], S1, msgbe[lvl*HH + h] * S0);
    }
}

// ---------------------------------------------------------------
// x += LN(silu([x, msum] @ upd_W + upd_b)); accumulate level mean.
__global__ void __launch_bounds__(128) k_upd(
    const float* __restrict__ updW, const float* __restrict__ updb,
    const float* __restrict__ updg, const float* __restrict__ updbe, int lvl)
{
    __shared__ float us[2*HH];
    __shared__ float rp[4], rq[4];
    __shared__ float s_mu, s_rstd;
    int i = blockIdx.x;
    int h = threadIdx.x;
    int warp = h >> 5, lane = h & 31;

    us[h]      = g_x[i*HH + h];
    us[HH + h] = g_msum[i*HH + h];
    __syncthreads();

    const float* W = updW + (size_t)lvl*2*HH*HH;
    float acc = updb[lvl*HH + h];
    #pragma unroll 4
    for (int k = 0; k < 2*HH; k++) acc = fmaf(us[k], W[k*HH + h], acc);

    float s = silu_f(acc);

    float p = warp_sum(s);
    float q = warp_sum(s*s);
    if (lane == 0) { rp[warp] = p; rq[warp] = q; }
    __syncthreads();
    if (h == 0) {
        float P = rp[0]+rp[1]+rp[2]+rp[3];
        float Q = rq[0]+rq[1]+rq[2]+rq[3];
        float mu = P * (1.f/HH);
        s_mu = mu;
        s_rstd = rsqrtf(fmaf(-mu, mu, Q * (1.f/HH)) + LN_EPS);
    }
    __syncthreads();

    float m  = fmaf((s - s_mu) * s_rstd, updg[lvl*HH + h], updbe[lvl*HH + h]);
    float xn = us[h] + m;
    g_x[i*HH + h] = xn;
    atomicAdd(&g_lmean[lvl*HH + h], xn * (1.f/NN));
}

// ---------------------------------------------------------------
__global__ void __launch_bounds__(256) k_final(
    const float* __restrict__ fpW, const float* __restrict__ fpb,
    const float* __restrict__ fpg, const float* __restrict__ fpbe,
    float* __restrict__ out)
{
    __shared__ float cs[NLVL*HH];
    __shared__ float rp[8], rq[8];
    __shared__ float s_mu, s_rstd;
    int t = threadIdx.x;
    int warp = t >> 5, lane = t & 31;

    for (int k = t; k < NLVL*HH; k += 256) cs[k] = g_lmean[k];
    __syncthreads();

    float acc = fpb[t];
    #pragma unroll 4
    for (int k = 0; k < NLVL*HH; k++) acc = fmaf(cs[k], fpW[k*DD + t], acc);

    float p = warp_sum(acc);
    float q = warp_sum(acc*acc);
    if (lane == 0) { rp[warp] = p; rq[warp] = q; }
    __syncthreads();
    if (t == 0) {
        float P = 0.f, Q = 0.f;
        #pragma unroll
        for (int w = 0; w < 8; w++) { P += rp[w]; Q += rq[w]; }
        float mu = P * (1.f/DD);
        s_mu = mu;
        s_rstd = rsqrtf(fmaf(-mu, mu, Q * (1.f/DD)) + LN_EPS);
    }
    __syncthreads();

    out[t] = fmaf((acc - s_mu) * s_rstd, fpg[t], fpbe[t]);
}

// ---------------------------------------------------------------
extern "C" void kernel_launch(void* const* d_in, const int* in_sizes, int n_in,
                              void* d_out, int out_size) {
    const int*   an    = (const int*)  d_in[0];
    const float* pos   = (const float*)d_in[1];
    const float* emb   = (const float*)d_in[2];
    const float* deW   = (const float*)d_in[3];
    const float* deb   = (const float*)d_in[4];
    const float* deg   = (const float*)d_in[5];
    const float* debe  = (const float*)d_in[6];
    const float* msgW  = (const float*)d_in[7];
    const float* msgb  = (const float*)d_in[8];
    const float* msgg  = (const float*)d_in[9];
    const float* msgbe = (const float*)d_in[10];
    const float* updW  = (const float*)d_in[11];
    const float* updb  = (const float*)d_in[12];
    const float* updg  = (const float*)d_in[13];
    const float* updbe = (const float*)d_in[14];
    const float* fpW   = (const float*)d_in[15];
    const float* fpb   = (const float*)d_in[16];
    const float* fpg   = (const float*)d_in[17];
    const float* fpbe  = (const float*)d_in[18];
    float* out = (float*)d_out;

    k_init<<<512, 256>>>(an, emb);
    k_ew<<<dim3(128, 1024), 256>>>(pos, deW, deb, deg, debe);
    for (int lvl = 0; lvl < NLVL; lvl++) {
        k_preprj<<<128, 128>>>(msgW, msgb, lvl);
        if (lvl == 0) k_msum<true><<<1024, 256>>>(msgg, msgbe, lvl);
        else          k_msum<false><<<1024, 256>>>(msgg, msgbe, lvl);
        k_upd<<<1024, 128>>>(updW, updb, updg, updbe, lvl);
    }
    k_final<<<1, 256>>>(fpW, fpb, fpg, fpbe, out);
}